// round 1
// baseline (speedup 1.0000x reference)
#include <cuda_runtime.h>

#define TPAD 68   // 64 + 4 pad: keeps float4 smem alignment, breaks 64-stride bank conflicts

// Scratch (allocation-free rule: device globals)
__device__ float g_x[4u * 1024u * 1024u];  // attention output, [B*N, D]
__device__ float g_h[4u * 1024u * 1024u];  // MLP hidden,      [B*N, D]

// ---------------------------------------------------------------------------
// Fused attention: ctx = softmax(Q K^T * scale) @ V  +  pe @ V
// One CTA per (b, h, q-tile of 64). Flash-style online softmax over 16 key
// tiles; second accumulator for the (non-rescaled) pe @ V term.
// Output written directly in [b, n, h*C + c] layout for the MLP.
// ---------------------------------------------------------------------------
__global__ __launch_bounds__(256, 2)
void attn_kernel(const float* __restrict__ q, const float* __restrict__ k,
                 const float* __restrict__ v, const float* __restrict__ pe,
                 float* __restrict__ xout)
{
    extern __shared__ float sm[];
    float (*Qs)[TPAD] = (float(*)[TPAD])(sm);
    float (*Ks)[TPAD] = (float(*)[TPAD])(sm + 1 * 64 * TPAD);
    float (*Vs)[TPAD] = (float(*)[TPAD])(sm + 2 * 64 * TPAD);
    float (*Es)[TPAD] = (float(*)[TPAD])(sm + 3 * 64 * TPAD);  // pe tile
    float (*Ps)[TPAD] = (float(*)[TPAD])(sm + 4 * 64 * TPAD);  // exp(S - m)

    const int b  = blockIdx.x;          // batch fastest -> pe tiles reused in L2 across b
    const int h  = blockIdx.y;
    const int q0 = blockIdx.z * 64;
    const int tid = threadIdx.x;
    const int tx = tid & 15, ty = tid >> 4;
    const float scale = 0.125f;         // C^-0.5, C=64

    const float* qb  = q  + ((size_t)(b * 16 + h) * 1024 + q0) * 64;
    const float* kb  = k  + (size_t)(b * 16 + h) * 1024 * 64;
    const float* vb  = v  + (size_t)(b * 16 + h) * 1024 * 64;
    const float* peb = pe + ((size_t)h * 1024 + q0) * 1024;

    // Load Q tile (resident for whole kernel)
    #pragma unroll
    for (int i = tid; i < 1024; i += 256) {
        int r = i >> 4, c = (i & 15) << 2;
        *(float4*)&Qs[r][c] = *(const float4*)(qb + r * 64 + c);
    }

    float accs[4][4] = {};   // softmax part (online-rescaled)
    float accp[4][4] = {};   // pe @ V part
    float rm[4], rl[4];      // per-row running max / sum (replicated across tx,
                             // kept consistent via butterfly allreduce)
    #pragma unroll
    for (int i = 0; i < 4; ++i) { rm[i] = -1e30f; rl[i] = 0.f; }

    for (int kt = 0; kt < 16; ++kt) {
        const int k0 = kt * 64;
        #pragma unroll
        for (int i = tid; i < 1024; i += 256) {
            int r = i >> 4, c = (i & 15) << 2;
            *(float4*)&Ks[r][c] = *(const float4*)(kb + (size_t)(k0 + r) * 64 + c);
            *(float4*)&Vs[r][c] = *(const float4*)(vb + (size_t)(k0 + r) * 64 + c);
            *(float4*)&Es[r][c] = *(const float4*)(peb + (size_t)r * 1024 + k0 + c);
        }
        __syncthreads();

        // S = Q @ K^T (4x4 per thread)
        float s[4][4] = {};
        #pragma unroll
        for (int kk = 0; kk < 64; ++kk) {
            float a[4], bb[4];
            #pragma unroll
            for (int i = 0; i < 4; ++i) a[i]  = Qs[ty * 4 + i][kk];
            #pragma unroll
            for (int j = 0; j < 4; ++j) bb[j] = Ks[tx * 4 + j][kk];
            #pragma unroll
            for (int i = 0; i < 4; ++i)
                #pragma unroll
                for (int j = 0; j < 4; ++j)
                    s[i][j] += a[i] * bb[j];
        }

        // Online softmax update. Row r = ty*4+i lives across the 16 tx lanes of
        // one warp half; xor masks 1..8 stay inside the half.
        #pragma unroll
        for (int i = 0; i < 4; ++i) {
            const int row = ty * 4 + i;
            float tm = -1e30f;
            #pragma unroll
            for (int j = 0; j < 4; ++j) { s[i][j] *= scale; tm = fmaxf(tm, s[i][j]); }
            #pragma unroll
            for (int m = 1; m < 16; m <<= 1)
                tm = fmaxf(tm, __shfl_xor_sync(0xffffffffu, tm, m));
            const float m_new = fmaxf(rm[i], tm);
            const float f = __expf(rm[i] - m_new);
            float sum = 0.f;
            #pragma unroll
            for (int j = 0; j < 4; ++j) {
                float p = __expf(s[i][j] - m_new);
                Ps[row][tx * 4 + j] = p;
                sum += p;
            }
            #pragma unroll
            for (int m = 1; m < 16; m <<= 1)
                sum += __shfl_xor_sync(0xffffffffu, sum, m);
            rl[i] = rl[i] * f + sum;
            rm[i] = m_new;
            #pragma unroll
            for (int j = 0; j < 4; ++j) accs[i][j] *= f;
        }
        __syncthreads();

        // accs += P @ V ; accp += E @ V
        #pragma unroll
        for (int kk = 0; kk < 64; ++kk) {
            float4 b4 = *(const float4*)&Vs[kk][tx * 4];
            float bv[4] = {b4.x, b4.y, b4.z, b4.w};
            float ap[4], ae[4];
            #pragma unroll
            for (int i = 0; i < 4; ++i) {
                ap[i] = Ps[ty * 4 + i][kk];
                ae[i] = Es[ty * 4 + i][kk];
            }
            #pragma unroll
            for (int i = 0; i < 4; ++i)
                #pragma unroll
                for (int j = 0; j < 4; ++j) {
                    accs[i][j] += ap[i] * bv[j];
                    accp[i][j] += ae[i] * bv[j];
                }
        }
        __syncthreads();
    }

    // Epilogue: ctx = accs / l + accp, written as [b, n, h*64 + c]
    #pragma unroll
    for (int i = 0; i < 4; ++i) {
        const float linv = 1.f / rl[i];
        float* dst = xout + ((size_t)b * 1024 + q0 + ty * 4 + i) * 1024 + h * 64 + tx * 4;
        float4 o;
        o.x = accs[i][0] * linv + accp[i][0];
        o.y = accs[i][1] * linv + accp[i][1];
        o.z = accs[i][2] * linv + accp[i][2];
        o.w = accs[i][3] * linv + accp[i][3];
        *(float4*)dst = o;
    }
}

// ---------------------------------------------------------------------------
// MLP GEMM: out[M,1024] = A[M,1024] @ W[1024,1024] + bias, optional SiLU.
// 64x64 CTA tile, 256 threads, 4x4 per thread, K in chunks of 64.
// ---------------------------------------------------------------------------
__global__ __launch_bounds__(256)
void mlp_gemm(const float* __restrict__ A, const float* __restrict__ W,
              const float* __restrict__ bias, float* __restrict__ out, int act)
{
    __shared__ float As[64][TPAD];
    __shared__ float Bs[64][TPAD];
    const int r0 = blockIdx.y * 64, o0 = blockIdx.x * 64;
    const int tid = threadIdx.x, tx = tid & 15, ty = tid >> 4;

    float acc[4][4] = {};
    for (int k0 = 0; k0 < 1024; k0 += 64) {
        #pragma unroll
        for (int i = tid; i < 1024; i += 256) {
            int r = i >> 4, c = (i & 15) << 2;
            *(float4*)&As[r][c] = *(const float4*)(A + (size_t)(r0 + r) * 1024 + k0 + c);
            *(float4*)&Bs[r][c] = *(const float4*)(W + (size_t)(k0 + r) * 1024 + o0 + c);
        }
        __syncthreads();
        #pragma unroll
        for (int kk = 0; kk < 64; ++kk) {
            float4 b4 = *(const float4*)&Bs[kk][tx * 4];
            float bv[4] = {b4.x, b4.y, b4.z, b4.w};
            float av[4];
            #pragma unroll
            for (int i = 0; i < 4; ++i) av[i] = As[ty * 4 + i][kk];
            #pragma unroll
            for (int i = 0; i < 4; ++i)
                #pragma unroll
                for (int j = 0; j < 4; ++j)
                    acc[i][j] += av[i] * bv[j];
        }
        __syncthreads();
    }

    #pragma unroll
    for (int i = 0; i < 4; ++i) {
        float* dst = out + (size_t)(r0 + ty * 4 + i) * 1024 + o0 + tx * 4;
        float4 o;
        float r[4];
        #pragma unroll
        for (int j = 0; j < 4; ++j) {
            float x = acc[i][j] + bias[o0 + tx * 4 + j];
            if (act) x = x / (1.f + __expf(-x));   // SiLU
            r[j] = x;
        }
        o.x = r[0]; o.y = r[1]; o.z = r[2]; o.w = r[3];
        *(float4*)dst = o;
    }
}

// ---------------------------------------------------------------------------
extern "C" void kernel_launch(void* const* d_in, const int* in_sizes, int n_in,
                              void* d_out, int out_size)
{
    const float* q  = (const float*)d_in[0];
    const float* k  = (const float*)d_in[1];
    const float* v  = (const float*)d_in[2];
    const float* pe = (const float*)d_in[3];
    const float* w1 = (const float*)d_in[4];
    const float* b1 = (const float*)d_in[5];
    const float* w2 = (const float*)d_in[6];
    const float* b2 = (const float*)d_in[7];
    float* out = (float*)d_out;

    float *xp = nullptr, *hp = nullptr;
    cudaGetSymbolAddress((void**)&xp, g_x);
    cudaGetSymbolAddress((void**)&hp, g_h);

    const int ATTN_SMEM = 5 * 64 * TPAD * (int)sizeof(float);  // ~87 KB
    cudaFuncSetAttribute(attn_kernel, cudaFuncAttributeMaxDynamicSharedMemorySize,
                         ATTN_SMEM);

    // Attention + pe@V fused, output in [B*N, D] layout
    attn_kernel<<<dim3(4, 16, 16), 256, ATTN_SMEM>>>(q, k, v, pe, xp);
    // fc1 + SiLU
    mlp_gemm<<<dim3(16, 64), 256>>>(xp, w1, b1, hp, 1);
    // fc2 + bias
    mlp_gemm<<<dim3(16, 64), 256>>>(hp, w2, b2, out, 0);
}

// round 2
// speedup vs baseline: 2.0843x; 2.0843x over previous
#include <cuda_runtime.h>
#include <cstdint>

#define SP 68   // 64 + 4 pad

// Scratch (allocation-free rule: device globals)
__device__ float g_x[4194304];  // attention output, [B*N, D]
__device__ float g_h[4194304];  // MLP hidden,      [B*N, D]

__device__ __forceinline__ float f2tf(float x) {
    uint32_t u;
    asm("cvt.rna.tf32.f32 %0, %1;" : "=r"(u) : "f"(x));
    return __uint_as_float(u);
}

__device__ __forceinline__ void ld_cvt4(float* dst, const float* src) {
    float4 t = *(const float4*)src;
    dst[0] = f2tf(t.x); dst[1] = f2tf(t.y); dst[2] = f2tf(t.z); dst[3] = f2tf(t.w);
}

// D += A @ B  (m16n8k8, tf32 in, fp32 accumulate)
__device__ __forceinline__ void mma8(float* c, const uint32_t* a, const uint32_t* b) {
    asm volatile("mma.sync.aligned.m16n8k8.row.col.f32.tf32.tf32.f32 "
        "{%0,%1,%2,%3}, {%4,%5,%6,%7}, {%8,%9}, {%0,%1,%2,%3};"
        : "+f"(c[0]), "+f"(c[1]), "+f"(c[2]), "+f"(c[3])
        : "r"(a[0]), "r"(a[1]), "r"(a[2]), "r"(a[3]), "r"(b[0]), "r"(b[1]));
}

// ---------------------------------------------------------------------------
// Fused attention: ctx = softmax(Q K^T * scale) @ V  +  pe @ V   (tensor cores)
// CTA = (b, h, 128-row q-tile). 8 warps; warp w owns q-rows [16w, 16w+16).
// Flash-style online softmax done on MMA C fragments (rows never leave the
// warp). Output written in [b, n, h*64 + c] layout for the MLP.
// ---------------------------------------------------------------------------
__global__ __launch_bounds__(256, 1)
void attn_kernel(const float* __restrict__ q, const float* __restrict__ k,
                 const float* __restrict__ v, const float* __restrict__ pe,
                 float* __restrict__ xout)
{
    extern __shared__ float sm[];
    float (*Qs)[SP] = (float(*)[SP])sm;                  // 128 x 64 (tf32)
    float (*Ps)[SP] = (float(*)[SP])(sm + 128 * SP);     // 128 x 64 (tf32 probs)
    float (*Es)[SP] = (float(*)[SP])(sm + 256 * SP);     // 128 x 64 (pe tile)
    float (*Ks)[SP] = (float(*)[SP])(sm + 384 * SP);     // 64 x 64
    float (*Vs)[SP] = (float(*)[SP])(sm + 448 * SP);     // 64 x 64

    const int b = blockIdx.x, h = blockIdx.y, q0 = blockIdx.z * 128;
    const int tid  = threadIdx.x;
    const int lane = tid & 31, warp = tid >> 5;
    const int quad = lane >> 2, qt = lane & 3;
    const int rl0 = warp * 16 + quad;   // fragment row (lo half)
    const int rh0 = rl0 + 8;            // fragment row (hi half)
    const float scale = 0.125f;         // C^-0.5

    const float* qb  = q  + ((size_t)(b * 16 + h) * 1024 + q0) * 64;
    const float* kb  = k  + (size_t)(b * 16 + h) * 65536;
    const float* vb  = v  + (size_t)(b * 16 + h) * 65536;
    const float* peb = pe + ((size_t)h * 1024 + q0) * 1024;

    // Q tile (resident, tf32)
    for (int i = tid; i < 2048; i += 256) {
        int r = i >> 4, c = (i & 15) << 2;
        ld_cvt4(&Qs[r][c], qb + r * 64 + c);
    }
    __syncthreads();

    // Preload Q A-fragments (fixed for whole kernel): 8 k-groups of 8
    uint32_t qa[8][4];
    #pragma unroll
    for (int kg = 0; kg < 8; ++kg) {
        qa[kg][0] = __float_as_uint(Qs[rl0][kg * 8 + qt]);
        qa[kg][1] = __float_as_uint(Qs[rh0][kg * 8 + qt]);
        qa[kg][2] = __float_as_uint(Qs[rl0][kg * 8 + 4 + qt]);
        qa[kg][3] = __float_as_uint(Qs[rh0][kg * 8 + 4 + qt]);
    }

    float os[8][4] = {};   // softmax @ V (online-rescaled)
    float op[8][4] = {};   // pe @ V
    float rm_lo = -1e30f, rm_hi = -1e30f, rl_lo = 0.f, rl_hi = 0.f;

    for (int kt = 0; kt < 16; ++kt) {
        const int k0 = kt * 64;
        __syncthreads();   // everyone done reading previous K/V/E tiles
        for (int i = tid; i < 1024; i += 256) {
            int r = i >> 4, c = (i & 15) << 2;
            ld_cvt4(&Ks[r][c], kb + (size_t)(k0 + r) * 64 + c);
            ld_cvt4(&Vs[r][c], vb + (size_t)(k0 + r) * 64 + c);
        }
        for (int i = tid; i < 2048; i += 256) {
            int r = i >> 4, c = (i & 15) << 2;
            ld_cvt4(&Es[r][c], peb + (size_t)r * 1024 + k0 + c);
        }
        __syncthreads();

        // ----- S = Q @ K^T : warp strip 16 x 64 -----
        float sacc[8][4] = {};
        #pragma unroll
        for (int kg = 0; kg < 8; ++kg) {
            #pragma unroll
            for (int ng = 0; ng < 8; ++ng) {
                uint32_t bf[2];
                bf[0] = __float_as_uint(Ks[ng * 8 + quad][kg * 8 + qt]);
                bf[1] = __float_as_uint(Ks[ng * 8 + quad][kg * 8 + 4 + qt]);
                mma8(sacc[ng], qa[kg], bf);
            }
        }

        // ----- online softmax on fragments (rows lo/hi owned by quad group) -----
        float tm_lo = -1e30f, tm_hi = -1e30f;
        #pragma unroll
        for (int ng = 0; ng < 8; ++ng) {
            tm_lo = fmaxf(tm_lo, fmaxf(sacc[ng][0], sacc[ng][1]));
            tm_hi = fmaxf(tm_hi, fmaxf(sacc[ng][2], sacc[ng][3]));
        }
        tm_lo *= scale; tm_hi *= scale;
        #pragma unroll
        for (int m = 1; m < 4; m <<= 1) {
            tm_lo = fmaxf(tm_lo, __shfl_xor_sync(0xffffffffu, tm_lo, m));
            tm_hi = fmaxf(tm_hi, __shfl_xor_sync(0xffffffffu, tm_hi, m));
        }
        const float mn_lo = fmaxf(rm_lo, tm_lo), mn_hi = fmaxf(rm_hi, tm_hi);
        const float f_lo = __expf(rm_lo - mn_lo), f_hi = __expf(rm_hi - mn_hi);
        float sum_lo = 0.f, sum_hi = 0.f;
        #pragma unroll
        for (int ng = 0; ng < 8; ++ng) {
            float p0 = __expf(sacc[ng][0] * scale - mn_lo);
            float p1 = __expf(sacc[ng][1] * scale - mn_lo);
            float p2 = __expf(sacc[ng][2] * scale - mn_hi);
            float p3 = __expf(sacc[ng][3] * scale - mn_hi);
            sum_lo += p0 + p1; sum_hi += p2 + p3;
            *(float2*)&Ps[rl0][ng * 8 + qt * 2] = make_float2(f2tf(p0), f2tf(p1));
            *(float2*)&Ps[rh0][ng * 8 + qt * 2] = make_float2(f2tf(p2), f2tf(p3));
        }
        #pragma unroll
        for (int m = 1; m < 4; m <<= 1) {
            sum_lo += __shfl_xor_sync(0xffffffffu, sum_lo, m);
            sum_hi += __shfl_xor_sync(0xffffffffu, sum_hi, m);
        }
        rl_lo = rl_lo * f_lo + sum_lo; rl_hi = rl_hi * f_hi + sum_hi;
        rm_lo = mn_lo; rm_hi = mn_hi;
        #pragma unroll
        for (int ng = 0; ng < 8; ++ng) {
            os[ng][0] *= f_lo; os[ng][1] *= f_lo;
            os[ng][2] *= f_hi; os[ng][3] *= f_hi;
        }
        __syncwarp();   // P strip: written and read by this warp only

        // ----- os += P @ V ; op += E @ V  (shared V B-fragments) -----
        #pragma unroll
        for (int kg = 0; kg < 8; ++kg) {
            uint32_t pa[4], ea[4];
            pa[0] = __float_as_uint(Ps[rl0][kg * 8 + qt]);
            pa[1] = __float_as_uint(Ps[rh0][kg * 8 + qt]);
            pa[2] = __float_as_uint(Ps[rl0][kg * 8 + 4 + qt]);
            pa[3] = __float_as_uint(Ps[rh0][kg * 8 + 4 + qt]);
            ea[0] = __float_as_uint(Es[rl0][kg * 8 + qt]);
            ea[1] = __float_as_uint(Es[rh0][kg * 8 + qt]);
            ea[2] = __float_as_uint(Es[rl0][kg * 8 + 4 + qt]);
            ea[3] = __float_as_uint(Es[rh0][kg * 8 + 4 + qt]);
            #pragma unroll
            for (int ng = 0; ng < 8; ++ng) {
                uint32_t bf[2];
                bf[0] = __float_as_uint(Vs[kg * 8 + qt][ng * 8 + quad]);
                bf[1] = __float_as_uint(Vs[kg * 8 + 4 + qt][ng * 8 + quad]);
                mma8(os[ng], pa, bf);
                mma8(op[ng], ea, bf);
            }
        }
    }

    // Epilogue: ctx = os / l + op, written as [b, n, h*64 + c]
    const float il_lo = 1.f / rl_lo, il_hi = 1.f / rl_hi;
    #pragma unroll
    for (int ng = 0; ng < 8; ++ng) {
        const int col = h * 64 + ng * 8 + qt * 2;
        float* d0 = xout + ((size_t)b * 1024 + q0 + rl0) * 1024 + col;
        float* d1 = xout + ((size_t)b * 1024 + q0 + rh0) * 1024 + col;
        *(float2*)d0 = make_float2(os[ng][0] * il_lo + op[ng][0],
                                   os[ng][1] * il_lo + op[ng][1]);
        *(float2*)d1 = make_float2(os[ng][2] * il_hi + op[ng][2],
                                   os[ng][3] * il_hi + op[ng][3]);
    }
}

// ---------------------------------------------------------------------------
// MLP GEMM: out[M,1024] = act(A[M,1024] @ W[1024,1024] + bias)
// CTA tile 128x64, 8 warps of 16x64, tf32 MMA, K chunks of 64.
// ---------------------------------------------------------------------------
__global__ __launch_bounds__(256, 1)
void mlp_gemm(const float* __restrict__ A, const float* __restrict__ W,
              const float* __restrict__ bias, float* __restrict__ out, int act)
{
    extern __shared__ float sm[];
    float (*As)[SP] = (float(*)[SP])sm;              // 128 x 64
    float (*Ws)[SP] = (float(*)[SP])(sm + 128 * SP); // 64 x 64
    const int r0 = blockIdx.y * 128, o0 = blockIdx.x * 64;
    const int tid = threadIdx.x, lane = tid & 31, warp = tid >> 5;
    const int quad = lane >> 2, qt = lane & 3;
    const int rl0 = warp * 16 + quad, rh0 = rl0 + 8;

    float acc[8][4] = {};
    for (int k0 = 0; k0 < 1024; k0 += 64) {
        __syncthreads();
        for (int i = tid; i < 2048; i += 256) {
            int r = i >> 4, c = (i & 15) << 2;
            ld_cvt4(&As[r][c], A + (size_t)(r0 + r) * 1024 + k0 + c);
        }
        for (int i = tid; i < 1024; i += 256) {
            int r = i >> 4, c = (i & 15) << 2;
            ld_cvt4(&Ws[r][c], W + (size_t)(k0 + r) * 1024 + o0 + c);
        }
        __syncthreads();
        #pragma unroll
        for (int kg = 0; kg < 8; ++kg) {
            uint32_t a[4];
            a[0] = __float_as_uint(As[rl0][kg * 8 + qt]);
            a[1] = __float_as_uint(As[rh0][kg * 8 + qt]);
            a[2] = __float_as_uint(As[rl0][kg * 8 + 4 + qt]);
            a[3] = __float_as_uint(As[rh0][kg * 8 + 4 + qt]);
            #pragma unroll
            for (int ng = 0; ng < 8; ++ng) {
                uint32_t bf[2];
                bf[0] = __float_as_uint(Ws[kg * 8 + qt][ng * 8 + quad]);
                bf[1] = __float_as_uint(Ws[kg * 8 + 4 + qt][ng * 8 + quad]);
                mma8(acc[ng], a, bf);
            }
        }
    }

    #pragma unroll
    for (int ng = 0; ng < 8; ++ng) {
        const int col = o0 + ng * 8 + qt * 2;
        const float b0v = bias[col], b1v = bias[col + 1];
        float x0 = acc[ng][0] + b0v, x1 = acc[ng][1] + b1v;
        float x2 = acc[ng][2] + b0v, x3 = acc[ng][3] + b1v;
        if (act) {
            x0 = x0 / (1.f + __expf(-x0)); x1 = x1 / (1.f + __expf(-x1));
            x2 = x2 / (1.f + __expf(-x2)); x3 = x3 / (1.f + __expf(-x3));
        }
        *(float2*)(out + (size_t)(r0 + rl0) * 1024 + col) = make_float2(x0, x1);
        *(float2*)(out + (size_t)(r0 + rh0) * 1024 + col) = make_float2(x2, x3);
    }
}

// ---------------------------------------------------------------------------
extern "C" void kernel_launch(void* const* d_in, const int* in_sizes, int n_in,
                              void* d_out, int out_size)
{
    const float* q  = (const float*)d_in[0];
    const float* k  = (const float*)d_in[1];
    const float* v  = (const float*)d_in[2];
    const float* pe = (const float*)d_in[3];
    const float* w1 = (const float*)d_in[4];
    const float* b1 = (const float*)d_in[5];
    const float* w2 = (const float*)d_in[6];
    const float* b2 = (const float*)d_in[7];
    float* out = (float*)d_out;

    float *xp = nullptr, *hp = nullptr;
    cudaGetSymbolAddress((void**)&xp, g_x);
    cudaGetSymbolAddress((void**)&hp, g_h);

    const int ATTN_SMEM = 512 * SP * (int)sizeof(float);  // ~136 KB
    const int MLP_SMEM  = 192 * SP * (int)sizeof(float);  // ~51 KB
    cudaFuncSetAttribute(attn_kernel, cudaFuncAttributeMaxDynamicSharedMemorySize, ATTN_SMEM);
    cudaFuncSetAttribute(mlp_gemm,    cudaFuncAttributeMaxDynamicSharedMemorySize, MLP_SMEM);

    attn_kernel<<<dim3(4, 16, 8), 256, ATTN_SMEM>>>(q, k, v, pe, xp);
    mlp_gemm<<<dim3(16, 32), 256, MLP_SMEM>>>(xp, w1, b1, hp, 1);
    mlp_gemm<<<dim3(16, 32), 256, MLP_SMEM>>>(hp, w2, b2, out, 0);
}